// round 4
// baseline (speedup 1.0000x reference)
#include <cuda_runtime.h>
#include <cstdint>
#include <cstddef>

#define N_MAX 50000
#define E_MAX 500000

// ---------------- scratch (device globals: no allocations allowed) ----------------
__device__ float g_PQ[(size_t)N_MAX * 256];        // [N,256]: cols 0:128 = P = X@A1^T, 128:256 = Q = X@A2^T
__device__ float g_edge_m[(size_t)E_MAX * 128];    // [E,128]: first R = emb@A3^T, then leakyrelu(R+P+Q)
__device__ float g_B1[256 * 128];                  // rows 0:128 = A1, 128:256 = A2  (row o = weights, K=128)
__device__ float g_B3[128 * 128];                  // A3
__device__ float g_edge_e[E_MAX];
__device__ float g_rel_att[E_MAX];
__device__ float g_arow[N_MAX];
__device__ float g_erow[N_MAX];
__device__ float g_ecol[N_MAX];
__device__ float g_new_rank[N_MAX];

// ---------------- init: zero accumulators + output feature block ----------------
__global__ void k_init(float* __restrict__ out, int N) {
    int i = blockIdx.x * blockDim.x + threadIdx.x;
    int total = N * 128;
    if (i < total) out[i] = 0.0f;
    if (i < N) { g_arow[i] = 0.0f; g_erow[i] = 0.0f; g_ecol[i] = 0.0f; }
}

// ---------------- extract B1 (A1|A2 stacked) and B3 from a [128,384] ----------------
__global__ void k_prep(const float* __restrict__ a) {
    int i = blockIdx.x * blockDim.x + threadIdx.x;
    if (i < 256 * 128) {
        int o = i >> 7, k = i & 127;
        g_B1[i] = (o < 128) ? a[o * 384 + k] : a[(o - 128) * 384 + 128 + k];
    }
    if (i < 128 * 128) {
        int o = i >> 7, k = i & 127;
        g_B3[i] = a[o * 384 + 256 + k];
    }
}

// ---------------- SGEMM: C[m][n] = sum_k A[m][k] * B[n][k], K = 128 fixed ----------------
// A rows: row < splitM -> A0[row], else A1[row - splitM] (handles concat of edge_embed arrays).
// mode 0: B = g_B1 (256 rows), C = g_PQ, ldc = 256
// mode 1: B = g_B3 (128 rows), C = g_edge_m, ldc = 128
__global__ __launch_bounds__(256) void k_sgemm(
    const float* __restrict__ A0, const float* __restrict__ A1, int splitM,
    int M, int mode)
{
    __shared__ __align__(16) float As[16][128];
    __shared__ __align__(16) float Bs[16][128];

    const float* __restrict__ B = (mode == 0) ? g_B1 : g_B3;
    float* __restrict__ C = (mode == 0) ? g_PQ : g_edge_m;
    const int ldc = (mode == 0) ? 256 : 128;

    int t  = threadIdx.x;
    int m0 = blockIdx.x * 128;
    int n0 = blockIdx.y * 128;
    int tx = t & 15, ty = t >> 4;

    float acc[8][8];
#pragma unroll
    for (int i = 0; i < 8; i++)
#pragma unroll
        for (int j = 0; j < 8; j++) acc[i][j] = 0.0f;

    int lr = t >> 2;          // 0..63
    int lc = (t & 3) * 4;     // 0,4,8,12

    for (int kc = 0; kc < 128; kc += 16) {
        // load A tile (128 rows x 16 k), transposed into As[k][m]
#pragma unroll
        for (int h = 0; h < 2; ++h) {
            int m = m0 + lr + h * 64;
            float4 v = make_float4(0.f, 0.f, 0.f, 0.f);
            if (m < M) {
                const float* arow = (m < splitM) ? (A0 + (size_t)m * 128)
                                                 : (A1 + (size_t)(m - splitM) * 128);
                v = *reinterpret_cast<const float4*>(arow + kc + lc);
            }
            As[lc + 0][lr + h * 64] = v.x;
            As[lc + 1][lr + h * 64] = v.y;
            As[lc + 2][lr + h * 64] = v.z;
            As[lc + 3][lr + h * 64] = v.w;
        }
        // load B tile
#pragma unroll
        for (int h = 0; h < 2; ++h) {
            int n = n0 + lr + h * 64;
            float4 v = *reinterpret_cast<const float4*>(B + (size_t)n * 128 + kc + lc);
            Bs[lc + 0][lr + h * 64] = v.x;
            Bs[lc + 1][lr + h * 64] = v.y;
            Bs[lc + 2][lr + h * 64] = v.z;
            Bs[lc + 3][lr + h * 64] = v.w;
        }
        __syncthreads();

#pragma unroll
        for (int kk = 0; kk < 16; ++kk) {
            float af[8], bf[8];
            float4 a0v = *reinterpret_cast<const float4*>(&As[kk][ty * 8]);
            float4 a1v = *reinterpret_cast<const float4*>(&As[kk][ty * 8 + 4]);
            float4 b0v = *reinterpret_cast<const float4*>(&Bs[kk][tx * 8]);
            float4 b1v = *reinterpret_cast<const float4*>(&Bs[kk][tx * 8 + 4]);
            af[0]=a0v.x; af[1]=a0v.y; af[2]=a0v.z; af[3]=a0v.w;
            af[4]=a1v.x; af[5]=a1v.y; af[6]=a1v.z; af[7]=a1v.w;
            bf[0]=b0v.x; bf[1]=b0v.y; bf[2]=b0v.z; bf[3]=b0v.w;
            bf[4]=b1v.x; bf[5]=b1v.y; bf[6]=b1v.z; bf[7]=b1v.w;
#pragma unroll
            for (int i = 0; i < 8; i++)
#pragma unroll
                for (int j = 0; j < 8; j++)
                    acc[i][j] = fmaf(af[i], bf[j], acc[i][j]);
        }
        __syncthreads();
    }

    // store
#pragma unroll
    for (int i = 0; i < 8; i++) {
        int m = m0 + ty * 8 + i;
        if (m >= M) continue;
        float* crow = C + (size_t)m * ldc + n0 + tx * 8;
        float4 v0 = make_float4(acc[i][0], acc[i][1], acc[i][2], acc[i][3]);
        float4 v1 = make_float4(acc[i][4], acc[i][5], acc[i][6], acc[i][7]);
        *reinterpret_cast<float4*>(crow)     = v0;
        *reinterpret_cast<float4*>(crow + 4) = v1;
    }
}

// ---------------- helpers ----------------
// NOTE: edge indices are int32 (JAX downcasts int64 without x64 enabled).
__device__ __forceinline__ void edge_src_dst(
    const int* __restrict__ edge, const int* __restrict__ nhop,
    int e, int E1, int E2, int& src, int& dst)
{
    if (e < E1) { src = edge[e]; dst = edge[E1 + e]; }
    else        { int e2 = e - E1; src = nhop[e2]; dst = nhop[E2 + e2]; }
}

// ---------------- per-edge: edge_m = leakyrelu(R + P[src] + Q[dst]); edge_e; a_rowsum ----------------
__global__ __launch_bounds__(128) void k_edge(
    const int* __restrict__ edge, const int* __restrict__ nhop,
    const float* __restrict__ a2, int E1, int E2)
{
    int e = blockIdx.x;
    int t = threadIdx.x;
    int src, dst;
    edge_src_dst(edge, nhop, e, E1, E2, src, dst);

    size_t eb = (size_t)e * 128;
    float m = g_edge_m[eb + t]
            + g_PQ[(size_t)src * 256 + t]
            + g_PQ[(size_t)dst * 256 + 128 + t];
    m = (m > 0.0f) ? m : 0.2f * m;
    g_edge_m[eb + t] = m;

    float p = m * a2[t];
#pragma unroll
    for (int off = 16; off > 0; off >>= 1)
        p += __shfl_down_sync(0xffffffffu, p, off);

    __shared__ float sred[4];
    if ((t & 31) == 0) sred[t >> 5] = p;
    __syncthreads();
    if (t == 0) {
        float s = sred[0] + sred[1] + sred[2] + sred[3];
        float lr = (s > 0.0f) ? s : 0.2f * s;
        float ee = expf(-lr);
        g_edge_e[e] = ee;
        atomicAdd(&g_arow[dst], ee);
    }
}

// ---------------- rel_att + e_rowsum ----------------
__global__ void k_rel(const int* __restrict__ edge, const int* __restrict__ nhop,
                      int E1, int E2, int E)
{
    int e = blockIdx.x * blockDim.x + threadIdx.x;
    if (e >= E) return;
    int src, dst;
    edge_src_dst(edge, nhop, e, E1, E2, src, dst);
    float as = g_arow[dst];
    if (as == 0.0f) as = 1e-12f;
    float r = g_edge_e[e] / as;
    g_rel_att[e] = r;
    atomicAdd(&g_erow[src], r);
}

// ---------------- val + e_colsum ----------------
__global__ void k_val(const int* __restrict__ edge, const int* __restrict__ nhop,
                      const float* __restrict__ entity_rank, int E1, int E2, int E)
{
    int e = blockIdx.x * blockDim.x + threadIdx.x;
    if (e >= E) return;
    int src, dst;
    edge_src_dst(edge, nhop, e, E1, E2, src, dst);
    float es = g_erow[src];
    if (es == 0.0f) es = 1e-12f;
    float v = g_rel_att[e] * entity_rank[src] / es;
    atomicAdd(&g_ecol[dst], v);
}

// ---------------- new_rank ----------------
__global__ void k_rank(float* __restrict__ out, int N, int out_size) {
    int n = blockIdx.x * blockDim.x + threadIdx.x;
    if (n >= N) return;
    float nr = 0.15f + 0.85f * g_ecol[n];
    g_new_rank[n] = nr;
    if (out_size >= N * 128 + N) out[(size_t)N * 128 + n] = nr;
}

// ---------------- scatter: h_prime[dst] += (rel_att * new_rank[src]) * edge_m[e] ----------------
__global__ __launch_bounds__(128) void k_scatter(
    const int* __restrict__ edge, const int* __restrict__ nhop,
    float* __restrict__ out, int E1, int E2, int E)
{
    int e = blockIdx.x * 4 + (threadIdx.x >> 5);
    if (e >= E) return;
    int lane = threadIdx.x & 31;
    int src, dst;
    edge_src_dst(edge, nhop, e, E1, E2, src, dst);
    float w = g_rel_att[e] * g_new_rank[src];
    float4 v = *reinterpret_cast<const float4*>(&g_edge_m[(size_t)e * 128 + lane * 4]);
    float* p = out + (size_t)dst * 128 + lane * 4;
    atomicAdd(p + 0, w * v.x);
    atomicAdd(p + 1, w * v.y);
    atomicAdd(p + 2, w * v.z);
    atomicAdd(p + 3, w * v.w);
}

// ---------------- in-place ELU ----------------
__global__ void k_elu(float* __restrict__ out, int total) {
    int i = blockIdx.x * blockDim.x + threadIdx.x;
    if (i >= total) return;
    float x = out[i];
    out[i] = (x > 0.0f) ? x : expm1f(x);
}

// ---------------- launch ----------------
extern "C" void kernel_launch(void* const* d_in, const int* in_sizes, int n_in,
                              void* d_out, int out_size) {
    const float* input       = (const float*)d_in[0];
    const int*   edge        = (const int*)d_in[1];
    const float* edge_embed  = (const float*)d_in[2];
    const int*   edge_nhop   = (const int*)d_in[3];
    const float* embed_nhop  = (const float*)d_in[4];
    const float* entity_rank = (const float*)d_in[5];
    const float* a           = (const float*)d_in[6];
    const float* a2          = (const float*)d_in[7];
    float* out = (float*)d_out;

    int N  = in_sizes[0] / 128;
    int E1 = in_sizes[1] / 2;
    int E2 = in_sizes[3] / 2;
    int E  = E1 + E2;

    k_init<<<(N * 128 + 255) / 256, 256>>>(out, N);
    k_prep<<<(256 * 128 + 255) / 256, 256>>>(a);

    dim3 g_pq((N + 127) / 128, 2);
    k_sgemm<<<g_pq, 256>>>(input, input, N, N, /*mode=*/0);

    dim3 g_r((E + 127) / 128, 1);
    k_sgemm<<<g_r, 256>>>(edge_embed, embed_nhop, E1, E, /*mode=*/1);

    k_edge<<<E, 128>>>(edge, edge_nhop, a2, E1, E2);
    k_rel<<<(E + 255) / 256, 256>>>(edge, edge_nhop, E1, E2, E);
    k_val<<<(E + 255) / 256, 256>>>(edge, edge_nhop, entity_rank, E1, E2, E);
    k_rank<<<(N + 255) / 256, 256>>>(out, N, out_size);
    k_scatter<<<(E + 3) / 4, 128>>>(edge, edge_nhop, out, E1, E2, E);
    k_elu<<<(N * 128 + 255) / 256, 256>>>(out, N * 128);
}